// round 4
// baseline (speedup 1.0000x reference)
#include <cuda_runtime.h>
#include <cuda_bf16.h>
#include <math.h>
#include <stdint.h>

// Problem constants
#define BB 32
#define TT 512
#define WW 250
#define DD 768
#define GG 3072       // 4*D
#define MROWS 8000    // B*W
#define H2 1536       // 2*D

// ------------------- device scratch (static globals; no allocs) -------------------
__device__ float g_feat[MROWS * DD];
__device__ float g_pre0[MROWS * GG];
__device__ float g_pre1[MROWS * GG];
__device__ float g_h1[MROWS * H2];
__device__ float g_h2[MROWS * H2];
__device__ float g_emis[MROWS * 2];
__device__ float g_hT[2][2][DD][BB];       // [parity][dir][k][b]  transposed h
__device__ float g_cst[2][DD][BB];         // [dir][unit][b]
__device__ int   g_first[MROWS];
__device__ unsigned char g_bp[BB][WW][2];
__device__ int g_w64 = 0;

// ------------------- int64 vs int32 detection -------------------
__global__ void detect_kernel(const int* __restrict__ w) {
    __shared__ int bad;
    if (threadIdx.x == 0) bad = 0;
    __syncthreads();
    for (int i = threadIdx.x; i < 8192; i += blockDim.x) {
        int v = w[2 * i + 1];
        if (v != 0 && v != -1) bad = 1;
    }
    __syncthreads();
    if (threadIdx.x == 0) g_w64 = bad ? 0 : 1;
}

// ------------------- first-subtoken index -------------------
__global__ void firstidx_kernel(const int* __restrict__ w) {
    int id = blockIdx.x * blockDim.x + threadIdx.x;
    if (id >= MROWS) return;
    int b = id / WW, ww = id % WW;
    int mul = g_w64 ? 2 : 1;
    const int* row = w + (size_t)b * TT * mul;
    int idx = TT - 1;
    for (int t = 0; t < TT; t++) {
        if (row[t * mul] == ww) { idx = t; break; }
    }
    g_first[id] = idx;
}

// ------------------- gather feat rows -------------------
__global__ void gather_kernel(const float* __restrict__ bert) {
    int row = blockIdx.x;
    int fi = g_first[row];
    int b = row / WW;
    const float4* src = (const float4*)(bert + ((size_t)b * TT + fi) * DD);
    float4* dst = (float4*)(g_feat + (size_t)row * DD);
    for (int i = threadIdx.x; i < DD / 4; i += blockDim.x) dst[i] = src[i];
}

// ------------------- fp32 GEMM: C[m][n] = sum_k A[m][k]*B[n][k] + bias[n] -------------------
#define BM 128
#define BN 128
#define BKK 8
__global__ __launch_bounds__(256) void gemm_bias_kernel(
    const float* __restrict__ A, const float* __restrict__ B,
    const float* __restrict__ bias, float* __restrict__ C,
    int M, int N, int K)
{
    __shared__ float As[2][BKK][BM];
    __shared__ float Bs[2][BKK][BN];
    int tid = threadIdx.x;
    int m0 = blockIdx.y * BM;
    int n0 = blockIdx.x * BN;

    int lr = tid >> 1;
    int lk = (tid & 1) * 4;
    int ty = tid >> 4;
    int tx = tid & 15;

    float acc[8][8];
#pragma unroll
    for (int r = 0; r < 8; r++)
#pragma unroll
        for (int c = 0; c < 8; c++) acc[r][c] = 0.f;

    int nIter = K / BKK;
    float4 aReg, bReg;

    {
        int m = m0 + lr;
        aReg = (m < M) ? *(const float4*)(A + (size_t)m * K + lk)
                       : make_float4(0.f, 0.f, 0.f, 0.f);
        bReg = *(const float4*)(B + (size_t)(n0 + lr) * K + lk);
        As[0][lk + 0][lr] = aReg.x; As[0][lk + 1][lr] = aReg.y;
        As[0][lk + 2][lr] = aReg.z; As[0][lk + 3][lr] = aReg.w;
        Bs[0][lk + 0][lr] = bReg.x; Bs[0][lk + 1][lr] = bReg.y;
        Bs[0][lk + 2][lr] = bReg.z; Bs[0][lk + 3][lr] = bReg.w;
    }
    __syncthreads();

    int cur = 0;
    for (int it = 0; it < nIter; ++it) {
        if (it + 1 < nIter) {
            int k0 = (it + 1) * BKK;
            int m = m0 + lr;
            aReg = (m < M) ? *(const float4*)(A + (size_t)m * K + k0 + lk)
                           : make_float4(0.f, 0.f, 0.f, 0.f);
            bReg = *(const float4*)(B + (size_t)(n0 + lr) * K + k0 + lk);
        }
#pragma unroll
        for (int k = 0; k < BKK; k++) {
            float a_[8], b_[8];
            *(float4*)&a_[0] = *(const float4*)&As[cur][k][ty * 8];
            *(float4*)&a_[4] = *(const float4*)&As[cur][k][ty * 8 + 4];
            *(float4*)&b_[0] = *(const float4*)&Bs[cur][k][tx * 8];
            *(float4*)&b_[4] = *(const float4*)&Bs[cur][k][tx * 8 + 4];
#pragma unroll
            for (int r = 0; r < 8; r++)
#pragma unroll
                for (int c = 0; c < 8; c++)
                    acc[r][c] = fmaf(a_[r], b_[c], acc[r][c]);
        }
        if (it + 1 < nIter) {
            cur ^= 1;
            As[cur][lk + 0][lr] = aReg.x; As[cur][lk + 1][lr] = aReg.y;
            As[cur][lk + 2][lr] = aReg.z; As[cur][lk + 3][lr] = aReg.w;
            Bs[cur][lk + 0][lr] = bReg.x; Bs[cur][lk + 1][lr] = bReg.y;
            Bs[cur][lk + 2][lr] = bReg.z; Bs[cur][lk + 3][lr] = bReg.w;
            __syncthreads();
        }
    }

#pragma unroll
    for (int r = 0; r < 8; r++) {
        int m = m0 + ty * 8 + r;
        if (m < M) {
#pragma unroll
            for (int c = 0; c < 8; c++) {
                int n = n0 + tx * 8 + c;
                C[(size_t)m * N + n] = acc[r][c] + bias[n];
            }
        }
    }
}

// ------------------- per-step LSTM kernel v2 -------------------
// Grid: 128 CTAs x 256 threads. CTAs 0-63: forward dir. 64-127: reverse dir.
// CTA owns 12 hidden units = 48 gate rows. 8 warps x 6 rows each.
// W rows live in SMEM (loaded per-warp, own rows only -> no block sync).
// h(t-1) read directly from transposed global buffer g_hT[k][b] via L1.
__global__ __launch_bounds__(256) void lstm_step_kernel(
    const float* __restrict__ preF, const float* __restrict__ preR,
    const float* __restrict__ whhF, const float* __restrict__ whhR,
    float* __restrict__ hout, int s)
{
    __shared__ float w_s[48 * DD];        // 147456 B
    __shared__ float gate_s[48 * BB];     //   6144 B

    int tid = threadIdx.x, bid = blockIdx.x;
    int dir = bid >> 6;
    int U0 = (bid & 63) * 12;
    const float* whh = dir ? whhR : whhF;
    const float* pre = dir ? preR : preF;
    int t = dir ? (WW - 1 - s) : s;

    int warp = tid >> 5, lane = tid & 31;
    int r0 = warp * 6;                    // this warp's 6 gate rows

    // Per-warp load of its own 6 W rows (row r -> gate g=r/12, unit u=r%12).
    // Each row: 192 float4, lanes stride it; only this warp reads these rows.
#pragma unroll
    for (int j = 0; j < 6; j++) {
        int r = r0 + j;
        int g = r / 12, u = r % 12;
        const float4* src = (const float4*)(whh + ((size_t)(g * DD + U0 + u)) * DD);
        float4* dst = (float4*)&w_s[r * DD];
        for (int k4 = lane; k4 < DD / 4; k4 += 32) dst[k4] = src[k4];
    }
    __syncwarp();

    float acc[6] = {0.f, 0.f, 0.f, 0.f, 0.f, 0.f};

    if (s > 0) {
        const float* hT = &g_hT[(s - 1) & 1][dir][0][0];  // [k][b]
#pragma unroll 2
        for (int k4 = 0; k4 < DD / 4; k4++) {
            // 4 consecutive k values; coalesced 32-bit loads (lane = batch)
            float h0 = __ldg(hT + (k4 * 4 + 0) * BB + lane);
            float h1 = __ldg(hT + (k4 * 4 + 1) * BB + lane);
            float h2v = __ldg(hT + (k4 * 4 + 2) * BB + lane);
            float h3 = __ldg(hT + (k4 * 4 + 3) * BB + lane);
#pragma unroll
            for (int j = 0; j < 6; j++) {
                float4 wv = *(const float4*)&w_s[(r0 + j) * DD + k4 * 4];
                acc[j] = fmaf(wv.x, h0, acc[j]);
                acc[j] = fmaf(wv.y, h1, acc[j]);
                acc[j] = fmaf(wv.z, h2v, acc[j]);
                acc[j] = fmaf(wv.w, h3, acc[j]);
            }
        }
    }

    // publish gate partials (lane = batch)
#pragma unroll
    for (int j = 0; j < 6; j++) gate_s[(r0 + j) * BB + lane] = acc[j];
    __syncthreads();

    // elementwise LSTM cell: 12 units x 32 batches = 384 items on 256 threads
    for (int item = tid; item < 12 * BB; item += 256) {
        int u = item >> 5, b = item & 31;
        size_t base = ((size_t)(b * WW + t)) * GG + U0 + u;
        float gi = gate_s[(0 * 12 + u) * BB + b] + pre[base + 0 * DD];
        float gf = gate_s[(1 * 12 + u) * BB + b] + pre[base + 1 * DD];
        float gg = gate_s[(2 * 12 + u) * BB + b] + pre[base + 2 * DD];
        float go = gate_s[(3 * 12 + u) * BB + b] + pre[base + 3 * DD];
        float iv = 1.f / (1.f + expf(-gi));
        float fv = 1.f / (1.f + expf(-gf));
        float gv = tanhf(gg);
        float ov = 1.f / (1.f + expf(-go));
        float cprev = (s > 0) ? g_cst[dir][U0 + u][b] : 0.f;
        float cc = fv * cprev + iv * gv;
        g_cst[dir][U0 + u][b] = cc;
        float hh = ov * tanhf(cc);
        g_hT[s & 1][dir][U0 + u][b] = hh;   // coalesced over b within each u
        hout[((size_t)(b * WW + t)) * H2 + dir * DD + U0 + u] = hh;
    }
}

// ------------------- emissions: linear (NT=2) + softmax -------------------
__global__ void emis_kernel(const float* __restrict__ h2,
                            const float* __restrict__ wlin,
                            const float* __restrict__ blin,
                            float* __restrict__ out)
{
    int row = blockIdx.x * 8 + (threadIdx.x >> 5);
    int lane = threadIdx.x & 31;
    if (row >= MROWS) return;
    const float4* hr = (const float4*)(h2 + (size_t)row * H2);
    const float4* w0 = (const float4*)(wlin);
    const float4* w1 = (const float4*)(wlin + H2);
    float a0 = 0.f, a1 = 0.f;
    for (int i = lane; i < H2 / 4; i += 32) {
        float4 hv = hr[i], x0 = w0[i], x1 = w1[i];
        a0 += hv.x * x0.x + hv.y * x0.y + hv.z * x0.z + hv.w * x0.w;
        a1 += hv.x * x1.x + hv.y * x1.y + hv.z * x1.z + hv.w * x1.w;
    }
#pragma unroll
    for (int o = 16; o; o >>= 1) {
        a0 += __shfl_down_sync(0xffffffffu, a0, o);
        a1 += __shfl_down_sync(0xffffffffu, a1, o);
    }
    if (lane == 0) {
        float l0 = a0 + blin[0], l1 = a1 + blin[1];
        float m = fmaxf(l0, l1);
        float e0 = expf(l0 - m), e1 = expf(l1 - m);
        float inv = 1.f / (e0 + e1);
        float p0 = e0 * inv, p1 = e1 * inv;
        g_emis[row * 2] = p0; g_emis[row * 2 + 1] = p1;
        out[MROWS + row * 2] = p0; out[MROWS + row * 2 + 1] = p1;
    }
}

// ------------------- CRF -------------------
__device__ __forceinline__ float lse2(float x, float y) {
    float m = fmaxf(x, y);
    return m + log1pf(expf(fminf(x, y) - m));
}

__global__ void crf_llh_kernel(const int* __restrict__ labels,
                               const float* __restrict__ start,
                               const float* __restrict__ endv,
                               const float* __restrict__ trans,
                               float* __restrict__ out)
{
    int b = threadIdx.x;
    __shared__ float red[BB];
    int mul = g_w64 ? 2 : 1;
    const int* lab = labels + (size_t)b * WW * mul;
    float t00 = trans[0], t01 = trans[1], t10 = trans[2], t11 = trans[3];

    int prev = lab[0];
    float num = start[prev];
    for (int s = 0; s < WW; s++) {
        int tg = lab[s * mul];
        num += g_emis[(b * WW + s) * 2 + tg];
        if (s > 0) num += trans[prev * 2 + tg];
        prev = tg;
    }
    num += endv[prev];

    float a0 = start[0] + g_emis[(b * WW) * 2 + 0];
    float a1 = start[1] + g_emis[(b * WW) * 2 + 1];
    for (int s = 1; s < WW; s++) {
        float e0 = g_emis[(b * WW + s) * 2 + 0];
        float e1 = g_emis[(b * WW + s) * 2 + 1];
        float x0 = lse2(a0 + t00, a1 + t10) + e0;
        float x1 = lse2(a0 + t01, a1 + t11) + e1;
        a0 = x0; a1 = x1;
    }
    float logZ = lse2(a0 + endv[0], a1 + endv[1]);
    red[b] = num - logZ;
    __syncthreads();
    if (b == 0) {
        float sum = 0.f;
        for (int i = 0; i < BB; i++) sum += red[i];
        out[MROWS + MROWS * 2] = -(sum / (float)BB);
    }
}

__global__ void crf_decode_kernel(const float* __restrict__ start,
                                  const float* __restrict__ endv,
                                  const float* __restrict__ trans,
                                  float* __restrict__ out)
{
    int b = threadIdx.x;
    float t00 = trans[0], t01 = trans[1], t10 = trans[2], t11 = trans[3];
    float s0 = start[0] + g_emis[(b * WW) * 2 + 0];
    float s1 = start[1] + g_emis[(b * WW) * 2 + 1];
    for (int s = 1; s < WW; s++) {
        float c00 = s0 + t00, c10 = s1 + t10;   // into tag 0
        float c01 = s0 + t01, c11 = s1 + t11;   // into tag 1
        unsigned char bp0 = (c10 > c00) ? 1 : 0;  // argmax: first max on tie
        unsigned char bp1 = (c11 > c01) ? 1 : 0;
        float e0 = g_emis[(b * WW + s) * 2 + 0];
        float e1 = g_emis[(b * WW + s) * 2 + 1];
        float n0 = fmaxf(c00, c10) + e0;
        float n1 = fmaxf(c01, c11) + e1;
        g_bp[b][s][0] = bp0; g_bp[b][s][1] = bp1;
        s0 = n0; s1 = n1;
    }
    int tag = (s1 + endv[1] > s0 + endv[0]) ? 1 : 0;
    out[b * WW + (WW - 1)] = (float)tag;
    for (int s = WW - 1; s >= 1; s--) {
        tag = (int)g_bp[b][s][tag];
        out[b * WW + (s - 1)] = (float)tag;
    }
}

// ------------------- host launcher -------------------
extern "C" void kernel_launch(void* const* d_in, const int* in_sizes, int n_in,
                              void* d_out, int out_size)
{
    const float* bert      = (const float*)d_in[0];
    const int*   words     = (const int*)d_in[1];
    const int*   labels    = (const int*)d_in[2];
    const float* w_ih_l0   = (const float*)d_in[3];
    const float* w_hh_l0   = (const float*)d_in[4];
    const float* b_l0      = (const float*)d_in[5];
    const float* w_ih_l0r  = (const float*)d_in[6];
    const float* w_hh_l0r  = (const float*)d_in[7];
    const float* b_l0r     = (const float*)d_in[8];
    const float* w_ih_l1   = (const float*)d_in[9];
    const float* w_hh_l1   = (const float*)d_in[10];
    const float* b_l1      = (const float*)d_in[11];
    const float* w_ih_l1r  = (const float*)d_in[12];
    const float* w_hh_l1r  = (const float*)d_in[13];
    const float* b_l1r     = (const float*)d_in[14];
    const float* w_lin     = (const float*)d_in[15];
    const float* b_lin     = (const float*)d_in[16];
    const float* crf_start = (const float*)d_in[17];
    const float* crf_end   = (const float*)d_in[18];
    const float* crf_trans = (const float*)d_in[19];
    float* out = (float*)d_out;

    float *pfeat, *ppre0, *ppre1, *ph1, *ph2;
    cudaGetSymbolAddress((void**)&pfeat, g_feat);
    cudaGetSymbolAddress((void**)&ppre0, g_pre0);
    cudaGetSymbolAddress((void**)&ppre1, g_pre1);
    cudaGetSymbolAddress((void**)&ph1, g_h1);
    cudaGetSymbolAddress((void**)&ph2, g_h2);

    detect_kernel<<<1, 256>>>(words);
    firstidx_kernel<<<(MROWS + 255) / 256, 256>>>(words);
    gather_kernel<<<MROWS, 192>>>(bert);

    dim3 gemm_grid(GG / BN, (MROWS + BM - 1) / BM);
    gemm_bias_kernel<<<gemm_grid, 256>>>(pfeat, w_ih_l0,  b_l0,  ppre0, MROWS, GG, DD);
    gemm_bias_kernel<<<gemm_grid, 256>>>(pfeat, w_ih_l0r, b_l0r, ppre1, MROWS, GG, DD);

    for (int s = 0; s < WW; s++)
        lstm_step_kernel<<<128, 256>>>(ppre0, ppre1, w_hh_l0, w_hh_l0r, ph1, s);

    gemm_bias_kernel<<<gemm_grid, 256>>>(ph1, w_ih_l1,  b_l1,  ppre0, MROWS, GG, H2);
    gemm_bias_kernel<<<gemm_grid, 256>>>(ph1, w_ih_l1r, b_l1r, ppre1, MROWS, GG, H2);

    for (int s = 0; s < WW; s++)
        lstm_step_kernel<<<128, 256>>>(ppre0, ppre1, w_hh_l1, w_hh_l1r, ph2, s);

    emis_kernel<<<MROWS / 8, 256>>>(ph2, w_lin, b_lin, out);
    crf_llh_kernel<<<1, BB>>>(labels, crf_start, crf_end, crf_trans, out);
    crf_decode_kernel<<<1, BB>>>(crf_start, crf_end, crf_trans, out);
}

// round 5
// speedup vs baseline: 1.4466x; 1.4466x over previous
#include <cuda_runtime.h>
#include <cuda_bf16.h>
#include <math.h>
#include <stdint.h>

// Problem constants
#define BB 32
#define TT 512
#define WW 250
#define DD 768
#define GG 3072       // 4*D
#define MROWS 8000    // B*W
#define H2 1536       // 2*D

// ------------------- device scratch (static globals; no allocs) -------------------
__device__ float g_feat[MROWS * DD];
__device__ float g_pre0[MROWS * GG];
__device__ float g_pre1[MROWS * GG];
__device__ float g_h1[MROWS * H2];
__device__ float g_h2[MROWS * H2];
__device__ float g_emis[MROWS * 2];
__device__ float g_hT[2][2][DD][BB];       // [parity][dir][k][b]  transposed h
__device__ int   g_first[MROWS];
__device__ unsigned char g_bp[BB][WW][2];
__device__ unsigned g_cnt[2] = {0, 0};     // per-dir barrier count
__device__ unsigned g_gen[2] = {0, 0};     // per-dir barrier generation
__device__ int g_w64 = 0;

// ------------------- int64 vs int32 detection -------------------
__global__ void detect_kernel(const int* __restrict__ w) {
    __shared__ int bad;
    if (threadIdx.x == 0) bad = 0;
    __syncthreads();
    for (int i = threadIdx.x; i < 8192; i += blockDim.x) {
        int v = w[2 * i + 1];
        if (v != 0 && v != -1) bad = 1;
    }
    __syncthreads();
    if (threadIdx.x == 0) g_w64 = bad ? 0 : 1;
}

// ------------------- first-subtoken index -------------------
__global__ void firstidx_kernel(const int* __restrict__ w) {
    int id = blockIdx.x * blockDim.x + threadIdx.x;
    if (id >= MROWS) return;
    int b = id / WW, ww = id % WW;
    int mul = g_w64 ? 2 : 1;
    const int* row = w + (size_t)b * TT * mul;
    int idx = TT - 1;
    for (int t = 0; t < TT; t++) {
        if (row[t * mul] == ww) { idx = t; break; }
    }
    g_first[id] = idx;
}

// ------------------- gather feat rows -------------------
__global__ void gather_kernel(const float* __restrict__ bert) {
    int row = blockIdx.x;
    int fi = g_first[row];
    int b = row / WW;
    const float4* src = (const float4*)(bert + ((size_t)b * TT + fi) * DD);
    float4* dst = (float4*)(g_feat + (size_t)row * DD);
    for (int i = threadIdx.x; i < DD / 4; i += blockDim.x) dst[i] = src[i];
}

// ------------------- fp32 GEMM: C[m][n] = sum_k A[m][k]*B[n][k] + bias[n] -------------------
#define BM 128
#define BN 128
#define BKK 8
__global__ __launch_bounds__(256) void gemm_bias_kernel(
    const float* __restrict__ A, const float* __restrict__ B,
    const float* __restrict__ bias, float* __restrict__ C,
    int M, int N, int K)
{
    __shared__ float As[2][BKK][BM];
    __shared__ float Bs[2][BKK][BN];
    int tid = threadIdx.x;
    int m0 = blockIdx.y * BM;
    int n0 = blockIdx.x * BN;

    int lr = tid >> 1;
    int lk = (tid & 1) * 4;
    int ty = tid >> 4;
    int tx = tid & 15;

    float acc[8][8];
#pragma unroll
    for (int r = 0; r < 8; r++)
#pragma unroll
        for (int c = 0; c < 8; c++) acc[r][c] = 0.f;

    int nIter = K / BKK;
    float4 aReg, bReg;

    {
        int m = m0 + lr;
        aReg = (m < M) ? *(const float4*)(A + (size_t)m * K + lk)
                       : make_float4(0.f, 0.f, 0.f, 0.f);
        bReg = *(const float4*)(B + (size_t)(n0 + lr) * K + lk);
        As[0][lk + 0][lr] = aReg.x; As[0][lk + 1][lr] = aReg.y;
        As[0][lk + 2][lr] = aReg.z; As[0][lk + 3][lr] = aReg.w;
        Bs[0][lk + 0][lr] = bReg.x; Bs[0][lk + 1][lr] = bReg.y;
        Bs[0][lk + 2][lr] = bReg.z; Bs[0][lk + 3][lr] = bReg.w;
    }
    __syncthreads();

    int cur = 0;
    for (int it = 0; it < nIter; ++it) {
        if (it + 1 < nIter) {
            int k0 = (it + 1) * BKK;
            int m = m0 + lr;
            aReg = (m < M) ? *(const float4*)(A + (size_t)m * K + k0 + lk)
                           : make_float4(0.f, 0.f, 0.f, 0.f);
            bReg = *(const float4*)(B + (size_t)(n0 + lr) * K + k0 + lk);
        }
#pragma unroll
        for (int k = 0; k < BKK; k++) {
            float a_[8], b_[8];
            *(float4*)&a_[0] = *(const float4*)&As[cur][k][ty * 8];
            *(float4*)&a_[4] = *(const float4*)&As[cur][k][ty * 8 + 4];
            *(float4*)&b_[0] = *(const float4*)&Bs[cur][k][tx * 8];
            *(float4*)&b_[4] = *(const float4*)&Bs[cur][k][tx * 8 + 4];
#pragma unroll
            for (int r = 0; r < 8; r++)
#pragma unroll
                for (int c = 0; c < 8; c++)
                    acc[r][c] = fmaf(a_[r], b_[c], acc[r][c]);
        }
        if (it + 1 < nIter) {
            cur ^= 1;
            As[cur][lk + 0][lr] = aReg.x; As[cur][lk + 1][lr] = aReg.y;
            As[cur][lk + 2][lr] = aReg.z; As[cur][lk + 3][lr] = aReg.w;
            Bs[cur][lk + 0][lr] = bReg.x; Bs[cur][lk + 1][lr] = bReg.y;
            Bs[cur][lk + 2][lr] = bReg.z; Bs[cur][lk + 3][lr] = bReg.w;
            __syncthreads();
        }
    }

#pragma unroll
    for (int r = 0; r < 8; r++) {
        int m = m0 + ty * 8 + r;
        if (m < M) {
#pragma unroll
            for (int c = 0; c < 8; c++) {
                int n = n0 + tx * 8 + c;
                C[(size_t)m * N + n] = acc[r][c] + bias[n];
            }
        }
    }
}

// ------------------- persistent LSTM layer kernel -------------------
// 128 CTAs x 256 threads; CTA 0-63: forward, 64-127: reverse. 12 units/CTA.
// W_hh tile resident in SMEM across all 250 steps. h exchanged via g_hT (L2),
// staged through double-buffered SMEM chunks. Per-direction grid barrier.
#define NCTA_DIR 64

__device__ __forceinline__ void dir_barrier(int dir) {
    __threadfence();
    __syncthreads();
    if (threadIdx.x == 0) {
        unsigned my = *(volatile unsigned*)&g_gen[dir];
        unsigned t = atomicAdd(&g_cnt[dir], 1u);
        if (t == NCTA_DIR - 1) {
            g_cnt[dir] = 0;
            __threadfence();
            atomicAdd(&g_gen[dir], 1u);
        } else {
            while (*(volatile unsigned*)&g_gen[dir] == my) { __nanosleep(64); }
            __threadfence();
        }
    }
    __syncthreads();
}

__global__ __launch_bounds__(256) void lstm_persist_kernel(
    const float* __restrict__ preF, const float* __restrict__ preR,
    const float* __restrict__ whhF, const float* __restrict__ whhR,
    float* __restrict__ hout)
{
    extern __shared__ float sm[];
    float* w_s    = sm;                      // 48*768   = 36864 floats
    float* h_s    = w_s + 48 * DD;           // 2*128*32 =  8192
    float* gate_s = h_s + 2 * 128 * BB;      // 48*32    =  1536
    float* c_s    = gate_s + 48 * BB;        // 12*32    =   384

    int tid = threadIdx.x, bid = blockIdx.x;
    int dir = bid >> 6;
    int U0 = (bid & 63) * 12;
    const float* whh = dir ? whhR : whhF;
    const float* pre = dir ? preR : preF;

    int warp = tid >> 5, lane = tid & 31;
    int r0 = warp * 6;                       // this warp's 6 gate rows

    // One-time cooperative W load. Row r (0..47): gate g=r/12, unit u=r%12.
    for (int idx = tid; idx < 48 * (DD / 4); idx += 256) {
        int r = idx / (DD / 4), k4 = idx % (DD / 4);
        int g = r / 12, u = r % 12;
        *(float4*)&w_s[r * DD + k4 * 4] =
            *(const float4*)(whh + ((size_t)(g * DD + U0 + u)) * DD + k4 * 4);
    }
    for (int idx = tid; idx < 12 * BB; idx += 256) c_s[idx] = 0.f;
    __syncthreads();

    for (int s = 0; s < WW; ++s) {
        int t = dir ? (WW - 1 - s) : s;
        float acc[6] = {0.f, 0.f, 0.f, 0.f, 0.f, 0.f};

        if (s > 0) {
            const float4* hp4 =
                (const float4*)&g_hT[(s - 1) & 1][dir][0][0];  // [k][b], 8 f4/row
            // stage chunk 0 (k 0..127)
#pragma unroll
            for (int j = 0; j < 4; j++) {
                int idx = tid + j * 256;             // 0..1023
                int kl = idx >> 3, q = idx & 7;
                *(float4*)&h_s[kl * BB + q * 4] = __ldcg(hp4 + (size_t)kl * 8 + q);
            }
            __syncthreads();

#pragma unroll 1
            for (int c = 0; c < 6; c++) {
                float4 nxt[4];
                if (c < 5) {
#pragma unroll
                    for (int j = 0; j < 4; j++) {
                        int idx = tid + j * 256;
                        int kl = idx >> 3, q = idx & 7;
                        nxt[j] = __ldcg(hp4 + (size_t)(c * 128 + 128 + kl) * 8 + q);
                    }
                }
                const float* hb = h_s + (c & 1) * (128 * BB);
#pragma unroll 4
                for (int kk = 0; kk < 128; kk += 4) {
                    float h0 = hb[(kk + 0) * BB + lane];
                    float h1 = hb[(kk + 1) * BB + lane];
                    float h2v = hb[(kk + 2) * BB + lane];
                    float h3 = hb[(kk + 3) * BB + lane];
#pragma unroll
                    for (int j = 0; j < 6; j++) {
                        float4 wv = *(const float4*)&w_s[(r0 + j) * DD + c * 128 + kk];
                        acc[j] = fmaf(wv.x, h0, acc[j]);
                        acc[j] = fmaf(wv.y, h1, acc[j]);
                        acc[j] = fmaf(wv.z, h2v, acc[j]);
                        acc[j] = fmaf(wv.w, h3, acc[j]);
                    }
                }
                if (c < 5) {
                    __syncthreads();   // all warps done reading buf (c+1)&1
                    float* hb2 = h_s + ((c + 1) & 1) * (128 * BB);
#pragma unroll
                    for (int j = 0; j < 4; j++) {
                        int idx = tid + j * 256;
                        int kl = idx >> 3, q = idx & 7;
                        *(float4*)&hb2[kl * BB + q * 4] = nxt[j];
                    }
                    __syncthreads();
                }
            }
        }

        // publish gate partials (lane = batch)
#pragma unroll
        for (int j = 0; j < 6; j++) gate_s[(r0 + j) * BB + lane] = acc[j];
        __syncthreads();

        // elementwise LSTM cell: 12 units x 32 batches = 384 items, strided
        for (int item = tid; item < 12 * BB; item += 256) {
            int u = item >> 5, b = item & 31;
            size_t base = ((size_t)(b * WW + t)) * GG + U0 + u;
            float gi = gate_s[(0 * 12 + u) * BB + b] + pre[base + 0 * DD];
            float gf = gate_s[(1 * 12 + u) * BB + b] + pre[base + 1 * DD];
            float gg = gate_s[(2 * 12 + u) * BB + b] + pre[base + 2 * DD];
            float go = gate_s[(3 * 12 + u) * BB + b] + pre[base + 3 * DD];
            float iv = 1.f / (1.f + expf(-gi));
            float fv = 1.f / (1.f + expf(-gf));
            float gv = tanhf(gg);
            float ov = 1.f / (1.f + expf(-go));
            float cc = fv * c_s[u * BB + b] + iv * gv;
            c_s[u * BB + b] = cc;
            float hh = ov * tanhf(cc);
            __stcg(&g_hT[s & 1][dir][U0 + u][b], hh);
            hout[((size_t)(b * WW + t)) * H2 + dir * DD + U0 + u] = hh;
        }

        if (s < WW - 1) dir_barrier(dir);
    }
}

// ------------------- emissions: linear (NT=2) + softmax -------------------
__global__ void emis_kernel(const float* __restrict__ h2,
                            const float* __restrict__ wlin,
                            const float* __restrict__ blin,
                            float* __restrict__ out)
{
    int row = blockIdx.x * 8 + (threadIdx.x >> 5);
    int lane = threadIdx.x & 31;
    if (row >= MROWS) return;
    const float4* hr = (const float4*)(h2 + (size_t)row * H2);
    const float4* w0 = (const float4*)(wlin);
    const float4* w1 = (const float4*)(wlin + H2);
    float a0 = 0.f, a1 = 0.f;
    for (int i = lane; i < H2 / 4; i += 32) {
        float4 hv = hr[i], x0 = w0[i], x1 = w1[i];
        a0 += hv.x * x0.x + hv.y * x0.y + hv.z * x0.z + hv.w * x0.w;
        a1 += hv.x * x1.x + hv.y * x1.y + hv.z * x1.z + hv.w * x1.w;
    }
#pragma unroll
    for (int o = 16; o; o >>= 1) {
        a0 += __shfl_down_sync(0xffffffffu, a0, o);
        a1 += __shfl_down_sync(0xffffffffu, a1, o);
    }
    if (lane == 0) {
        float l0 = a0 + blin[0], l1 = a1 + blin[1];
        float m = fmaxf(l0, l1);
        float e0 = expf(l0 - m), e1 = expf(l1 - m);
        float inv = 1.f / (e0 + e1);
        float p0 = e0 * inv, p1 = e1 * inv;
        g_emis[row * 2] = p0; g_emis[row * 2 + 1] = p1;
        out[MROWS + row * 2] = p0; out[MROWS + row * 2 + 1] = p1;
    }
}

// ------------------- CRF -------------------
__device__ __forceinline__ float lse2(float x, float y) {
    float m = fmaxf(x, y);
    return m + log1pf(expf(fminf(x, y) - m));
}

__global__ void crf_llh_kernel(const int* __restrict__ labels,
                               const float* __restrict__ start,
                               const float* __restrict__ endv,
                               const float* __restrict__ trans,
                               float* __restrict__ out)
{
    int b = threadIdx.x;
    __shared__ float red[BB];
    int mul = g_w64 ? 2 : 1;
    const int* lab = labels + (size_t)b * WW * mul;
    float t00 = trans[0], t01 = trans[1], t10 = trans[2], t11 = trans[3];

    int prev = lab[0];
    float num = start[prev];
    for (int s = 0; s < WW; s++) {
        int tg = lab[s * mul];
        num += g_emis[(b * WW + s) * 2 + tg];
        if (s > 0) num += trans[prev * 2 + tg];
        prev = tg;
    }
    num += endv[prev];

    float a0 = start[0] + g_emis[(b * WW) * 2 + 0];
    float a1 = start[1] + g_emis[(b * WW) * 2 + 1];
    for (int s = 1; s < WW; s++) {
        float e0 = g_emis[(b * WW + s) * 2 + 0];
        float e1 = g_emis[(b * WW + s) * 2 + 1];
        float x0 = lse2(a0 + t00, a1 + t10) + e0;
        float x1 = lse2(a0 + t01, a1 + t11) + e1;
        a0 = x0; a1 = x1;
    }
    float logZ = lse2(a0 + endv[0], a1 + endv[1]);
    red[b] = num - logZ;
    __syncthreads();
    if (b == 0) {
        float sum = 0.f;
        for (int i = 0; i < BB; i++) sum += red[i];
        out[MROWS + MROWS * 2] = -(sum / (float)BB);
    }
}

__global__ void crf_decode_kernel(const float* __restrict__ start,
                                  const float* __restrict__ endv,
                                  const float* __restrict__ trans,
                                  float* __restrict__ out)
{
    int b = threadIdx.x;
    float t00 = trans[0], t01 = trans[1], t10 = trans[2], t11 = trans[3];
    float s0 = start[0] + g_emis[(b * WW) * 2 + 0];
    float s1 = start[1] + g_emis[(b * WW) * 2 + 1];
    for (int s = 1; s < WW; s++) {
        float c00 = s0 + t00, c10 = s1 + t10;   // into tag 0
        float c01 = s0 + t01, c11 = s1 + t11;   // into tag 1
        unsigned char bp0 = (c10 > c00) ? 1 : 0;  // argmax: first max on tie
        unsigned char bp1 = (c11 > c01) ? 1 : 0;
        float e0 = g_emis[(b * WW + s) * 2 + 0];
        float e1 = g_emis[(b * WW + s) * 2 + 1];
        float n0 = fmaxf(c00, c10) + e0;
        float n1 = fmaxf(c01, c11) + e1;
        g_bp[b][s][0] = bp0; g_bp[b][s][1] = bp1;
        s0 = n0; s1 = n1;
    }
    int tag = (s1 + endv[1] > s0 + endv[0]) ? 1 : 0;
    out[b * WW + (WW - 1)] = (float)tag;
    for (int s = WW - 1; s >= 1; s--) {
        tag = (int)g_bp[b][s][tag];
        out[b * WW + (s - 1)] = (float)tag;
    }
}

// ------------------- host launcher -------------------
extern "C" void kernel_launch(void* const* d_in, const int* in_sizes, int n_in,
                              void* d_out, int out_size)
{
    const float* bert      = (const float*)d_in[0];
    const int*   words     = (const int*)d_in[1];
    const int*   labels    = (const int*)d_in[2];
    const float* w_ih_l0   = (const float*)d_in[3];
    const float* w_hh_l0   = (const float*)d_in[4];
    const float* b_l0      = (const float*)d_in[5];
    const float* w_ih_l0r  = (const float*)d_in[6];
    const float* w_hh_l0r  = (const float*)d_in[7];
    const float* b_l0r     = (const float*)d_in[8];
    const float* w_ih_l1   = (const float*)d_in[9];
    const float* w_hh_l1   = (const float*)d_in[10];
    const float* b_l1      = (const float*)d_in[11];
    const float* w_ih_l1r  = (const float*)d_in[12];
    const float* w_hh_l1r  = (const float*)d_in[13];
    const float* b_l1r     = (const float*)d_in[14];
    const float* w_lin     = (const float*)d_in[15];
    const float* b_lin     = (const float*)d_in[16];
    const float* crf_start = (const float*)d_in[17];
    const float* crf_end   = (const float*)d_in[18];
    const float* crf_trans = (const float*)d_in[19];
    float* out = (float*)d_out;

    float *pfeat, *ppre0, *ppre1, *ph1, *ph2;
    cudaGetSymbolAddress((void**)&pfeat, g_feat);
    cudaGetSymbolAddress((void**)&ppre0, g_pre0);
    cudaGetSymbolAddress((void**)&ppre1, g_pre1);
    cudaGetSymbolAddress((void**)&ph1, g_h1);
    cudaGetSymbolAddress((void**)&ph2, g_h2);

    const int lstm_smem = (48 * DD + 2 * 128 * BB + 48 * BB + 12 * BB) * 4; // 187,904 B
    cudaFuncSetAttribute(lstm_persist_kernel,
                         cudaFuncAttributeMaxDynamicSharedMemorySize, lstm_smem);

    detect_kernel<<<1, 256>>>(words);
    firstidx_kernel<<<(MROWS + 255) / 256, 256>>>(words);
    gather_kernel<<<MROWS, 192>>>(bert);

    dim3 gemm_grid(GG / BN, (MROWS + BM - 1) / BM);
    gemm_bias_kernel<<<gemm_grid, 256>>>(pfeat, w_ih_l0,  b_l0,  ppre0, MROWS, GG, DD);
    gemm_bias_kernel<<<gemm_grid, 256>>>(pfeat, w_ih_l0r, b_l0r, ppre1, MROWS, GG, DD);

    lstm_persist_kernel<<<128, 256, lstm_smem>>>(ppre0, ppre1, w_hh_l0, w_hh_l0r, ph1);

    gemm_bias_kernel<<<gemm_grid, 256>>>(ph1, w_ih_l1,  b_l1,  ppre0, MROWS, GG, H2);
    gemm_bias_kernel<<<gemm_grid, 256>>>(ph1, w_ih_l1r, b_l1r, ppre1, MROWS, GG, H2);

    lstm_persist_kernel<<<128, 256, lstm_smem>>>(ppre0, ppre1, w_hh_l1, w_hh_l1r, ph2);

    emis_kernel<<<MROWS / 8, 256>>>(ph2, w_lin, b_lin, out);
    crf_llh_kernel<<<1, BB>>>(labels, crf_start, crf_end, crf_trans, out);
    crf_decode_kernel<<<1, BB>>>(crf_start, crf_end, crf_trans, out);
}